// round 5
// baseline (speedup 1.0000x reference)
#include <cuda_runtime.h>

#define D1C   16
#define D2C   16
#define NCC   64
#define NCPCC 8

typedef unsigned long long u64;

__device__ __forceinline__ u64 pack2(float lo, float hi) {
    u64 r; asm("mov.b64 %0, {%1, %2};" : "=l"(r) : "f"(lo), "f"(hi)); return r;
}
__device__ __forceinline__ void unpack2(u64 v, float &lo, float &hi) {
    asm("mov.b64 {%0, %1}, %2;" : "=f"(lo), "=f"(hi) : "l"(v));
}
__device__ __forceinline__ u64 ffma2(u64 a, u64 b, u64 c) {
    u64 d; asm("fma.rn.f32x2 %0, %1, %2, %3;" : "=l"(d) : "l"(a), "l"(b), "l"(c)); return d;
}

__global__ void __launch_bounds__(256)
cluster_kernel(const float* __restrict__ x,
               const float* __restrict__ co,
               const float* __restrict__ ci,
               float* __restrict__ out, int n)
{
    __shared__ __align__(16) float s_oc[NCC * D1C];     // 4 KB, [c][d]
    __shared__ float s_on[NCC];                          // ||c||^2
    __shared__ float s_in[NCPCC * D2C * NCC];            // 32 KB, [k][d][o]
    __shared__ float s_inn[NCC * NCPCC];                 // ||ci[o][k]||^2

    const int tid = threadIdx.x;

    for (int idx = tid; idx < NCC * D1C; idx += blockDim.x)
        s_oc[idx] = co[idx];
    for (int idx = tid; idx < NCC * NCPCC * D2C; idx += blockDim.x) {
        int o  = idx >> 7;       // ci layout [o][k][d], 128 elems per o
        int kd = idx & 127;
        int k  = kd >> 4, d = kd & 15;
        s_in[(k * D2C + d) * NCC + o] = ci[idx];
    }
    __syncthreads();

    for (int o = tid; o < NCC; o += blockDim.x) {
        float s = 0.f;
        #pragma unroll
        for (int d = 0; d < D1C; d++) { float v = s_oc[o * D1C + d]; s += v * v; }
        s_on[o] = s;
    }
    for (int idx = tid; idx < NCC * NCPCC; idx += blockDim.x) {
        int o = idx >> 3, k = idx & 7;
        float s = 0.f;
        #pragma unroll
        for (int d = 0; d < D2C; d++) { float v = s_in[(k * D2C + d) * NCC + o]; s += v * v; }
        s_inn[idx] = s;
    }
    __syncthreads();

    const u64 z2 = 0ull;
    const int stride = gridDim.x * blockDim.x;

    for (int i = blockIdx.x * blockDim.x + tid; i < n; i += stride) {
        const float4* xp = (const float4*)(x + (size_t)i * (D1C + D2C));
        float4 a0 = xp[0], a1 = xp[1], a2 = xp[2], a3 = xp[3];  // x1
        float4 b0 = xp[4], b1 = xp[5], b2 = xp[6], b3 = xp[7];  // x2

        u64 px[8];
        px[0] = pack2(a0.x, a0.y); px[1] = pack2(a0.z, a0.w);
        px[2] = pack2(a1.x, a1.y); px[3] = pack2(a1.z, a1.w);
        px[4] = pack2(a2.x, a2.y); px[5] = pack2(a2.z, a2.w);
        px[6] = pack2(a3.x, a3.y); px[7] = pack2(a3.z, a3.w);

        // outer argmin: d = ||c||^2 - 2 x1.c  (strict <, first index wins)
        float best = 3.402823466e38f;
        int bo = 0;
        #pragma unroll 2
        for (int c = 0; c < NCC; c++) {
            const u64* cp = (const u64*)(s_oc + c * D1C);
            u64 ac = ffma2(px[0], cp[0], z2);
            u64 bc = ffma2(px[1], cp[1], z2);
            ac = ffma2(px[2], cp[2], ac);
            bc = ffma2(px[3], cp[3], bc);
            ac = ffma2(px[4], cp[4], ac);
            bc = ffma2(px[5], cp[5], bc);
            ac = ffma2(px[6], cp[6], ac);
            bc = ffma2(px[7], cp[7], bc);
            float al, ah, bl, bh;
            unpack2(ac, al, ah); unpack2(bc, bl, bh);
            float s  = (al + ah) + (bl + bh);
            float dd = fmaf(-2.f, s, s_on[c]);
            if (dd < best) { best = dd; bo = c; }
        }

        float x2r[16];
        x2r[0]=b0.x;  x2r[1]=b0.y;  x2r[2]=b0.z;  x2r[3]=b0.w;
        x2r[4]=b1.x;  x2r[5]=b1.y;  x2r[6]=b1.z;  x2r[7]=b1.w;
        x2r[8]=b2.x;  x2r[9]=b2.y;  x2r[10]=b2.z; x2r[11]=b2.w;
        x2r[12]=b3.x; x2r[13]=b3.y; x2r[14]=b3.z; x2r[15]=b3.w;

        const float* base = s_in + bo;   // [k][d][o], o fixed -> imm offsets
        float bestd = 3.402823466e38f;
        int bk = 0;
        #pragma unroll
        for (int k = 0; k < NCPCC; k++) {
            float s = 0.f;
            #pragma unroll
            for (int d = 0; d < D2C; d++)
                s = fmaf(x2r[d], base[(k * D2C + d) * NCC], s);
            float dd = fmaf(-2.f, s, s_inn[bo * NCPCC + k]);
            if (dd < bestd) { bestd = dd; bk = k; }
        }

        // Output dtype is float32 per metadata (indices are exactly
        // representable; 1.0-rel-err signature showed int writes read as
        // float denormals ~= 0).
        out[i] = (float)(bo * NCPCC + bk);
    }
}

extern "C" void kernel_launch(void* const* d_in, const int* in_sizes, int n_in,
                              void* d_out, int out_size)
{
    // Bind inputs by UNIQUE element counts — robust to metadata ordering.
    //   centers_outer: 64*16   = 1024
    //   centers_inner: 64*8*16 = 8192
    //   x:             N*32    (the remaining / largest one)
    const float* x  = 0;
    const float* co = 0;
    const float* ci = 0;
    long long x_elems = 0;
    for (int i = 0; i < n_in; i++) {
        int sz = in_sizes[i];
        if (sz == NCC * D1C)              co = (const float*)d_in[i];
        else if (sz == NCC * NCPCC * D2C) ci = (const float*)d_in[i];
        else { x = (const float*)d_in[i]; x_elems = sz; }
    }
    if (!x)  { x  = (const float*)d_in[0]; x_elems = in_sizes[0]; }
    if (!co)   co = (const float*)d_in[1];
    if (!ci)   ci = (const float*)d_in[2];

    float* out = (float*)d_out;
    int n = (int)(x_elems / (D1C + D2C));
    if (n <= 0 || n > out_size) n = out_size;

    int blocks = 592;  // 148 SMs * 4 CTAs, grid-stride
    cluster_kernel<<<blocks, 256>>>(x, co, ci, out, n);
}

// round 6
// speedup vs baseline: 1.3060x; 1.3060x over previous
#include <cuda_runtime.h>

#define D1C   16
#define D2C   16
#define NCC   64
#define NCPCC 8
// Inner o-block: 128 data floats + 8 norms + 4 pad = 140 floats (560B, 16B-aligned).
// Quad stride 35 == 3 (mod 8) -> distinct bo spread over all 8 quad-groups.
#define ISTRIDE 140

typedef unsigned long long u64;

__device__ __forceinline__ u64 ffma2(u64 a, u64 b, u64 c) {
    u64 d; asm("fma.rn.f32x2 %0, %1, %2, %3;" : "=l"(d) : "l"(a), "l"(b), "l"(c)); return d;
}
__device__ __forceinline__ float hsum2(u64 v) {
    float lo, hi;
    asm("mov.b64 {%0, %1}, %2;" : "=f"(lo), "=f"(hi) : "l"(v));
    return lo + hi;
}

__global__ void __launch_bounds__(256, 2)
cluster_kernel(const float* __restrict__ x,
               const float* __restrict__ co,
               const float* __restrict__ ci,
               float* __restrict__ out, int n)
{
    __shared__ __align__(16) float s_oc[NCC * D1C];     // outer centers [c][d], 4KB
    __shared__ __align__(16) float s_on[NCC];           // outer ||c||^2
    __shared__ __align__(16) float s_in[NCC * ISTRIDE]; // inner [o]{128 data | 8 norms | pad}, 35KB

    const int tid = threadIdx.x;

    for (int idx = tid; idx < NCC * D1C; idx += 256)
        s_oc[idx] = co[idx];
    for (int idx = tid; idx < NCC * NCPCC * D2C; idx += 256) {
        int o = idx >> 7, r = idx & 127;            // ci is [o][k][d]
        s_in[o * ISTRIDE + r] = ci[idx];
    }
    __syncthreads();

    for (int c = tid; c < NCC; c += 256) {
        float s = 0.f;
        #pragma unroll
        for (int d = 0; d < D1C; d++) { float v = s_oc[c * D1C + d]; s += v * v; }
        s_on[c] = s;
    }
    for (int idx = tid; idx < NCC * NCPCC; idx += 256) {
        int o = idx >> 3, k = idx & 7;
        float s = 0.f;
        #pragma unroll
        for (int d = 0; d < D2C; d++) { float v = s_in[o * ISTRIDE + k * D2C + d]; s += v * v; }
        s_in[o * ISTRIDE + 128 + k] = s;            // norms in the pad region
    }
    __syncthreads();

    const int GS = gridDim.x * blockDim.x;

    for (int i0 = blockIdx.x * blockDim.x + tid; i0 < n; i0 += 2 * GS) {
        int  i1   = i0 + GS;
        bool has1 = (i1 < n);

        // x row = 32 floats = 8 x 16B. ulonglong2 views give packed (x_d, x_d+1)
        // f32x2 operands directly from LDG.128 — no repacking instructions.
        const ulonglong2* p0 = (const ulonglong2*)(x + (size_t)i0 * 32);
        const ulonglong2* p1 = (const ulonglong2*)(x + (size_t)(has1 ? i1 : i0) * 32);

        ulonglong2 w00 = p0[0], w01 = p0[1], w02 = p0[2], w03 = p0[3]; // x1 of pt0
        ulonglong2 v00 = p0[4], v01 = p0[5], v02 = p0[6], v03 = p0[7]; // x2 of pt0
        ulonglong2 w10 = p1[0], w11 = p1[1], w12 = p1[2], w13 = p1[3]; // x1 of pt1
        ulonglong2 v10 = p1[4], v11 = p1[5], v12 = p1[6], v13 = p1[7]; // x2 of pt1

        u64 px0[8] = {w00.x, w00.y, w01.x, w01.y, w02.x, w02.y, w03.x, w03.y};
        u64 px1[8] = {w10.x, w10.y, w11.x, w11.y, w12.x, w12.y, w13.x, w13.y};

        // ---- outer argmin: d = ||c||^2 - 2 x1.c  (strict <, first wins) ----
        float best0 = 3.402823466e38f, best1 = 3.402823466e38f;
        int   bo0 = 0, bo1 = 0;

        #pragma unroll 2
        for (int cg = 0; cg < NCC / 4; cg++) {
            float4 nr = *(const float4*)(s_on + cg * 4);   // 4 norms, broadcast
            float nrr[4] = {nr.x, nr.y, nr.z, nr.w};
            #pragma unroll
            for (int j = 0; j < 4; j++) {
                int c = cg * 4 + j;
                const ulonglong2* cp = (const ulonglong2*)(s_oc + c * D1C);
                ulonglong2 m0 = cp[0], m1 = cp[1], m2 = cp[2], m3 = cp[3]; // 4x LDS.128 bcast

                u64 a0 = ffma2(px0[0], m0.x, 0ull);
                u64 a1 = ffma2(px1[0], m0.x, 0ull);
                a0 = ffma2(px0[1], m0.y, a0);  a1 = ffma2(px1[1], m0.y, a1);
                a0 = ffma2(px0[2], m1.x, a0);  a1 = ffma2(px1[2], m1.x, a1);
                a0 = ffma2(px0[3], m1.y, a0);  a1 = ffma2(px1[3], m1.y, a1);
                a0 = ffma2(px0[4], m2.x, a0);  a1 = ffma2(px1[4], m2.x, a1);
                a0 = ffma2(px0[5], m2.y, a0);  a1 = ffma2(px1[5], m2.y, a1);
                a0 = ffma2(px0[6], m3.x, a0);  a1 = ffma2(px1[6], m3.x, a1);
                a0 = ffma2(px0[7], m3.y, a0);  a1 = ffma2(px1[7], m3.y, a1);

                float dd0 = fmaf(-2.f, hsum2(a0), nrr[j]);
                float dd1 = fmaf(-2.f, hsum2(a1), nrr[j]);
                if (dd0 < best0) { best0 = dd0; bo0 = c; }
                if (dd1 < best1) { best1 = dd1; bo1 = c; }
            }
        }

        // ---- inner argmin over the 8 sub-centers of bo, both points fused ----
        u64 py0[8] = {v00.x, v00.y, v01.x, v01.y, v02.x, v02.y, v03.x, v03.y};
        u64 py1[8] = {v10.x, v10.y, v11.x, v11.y, v12.x, v12.y, v13.x, v13.y};

        const float* ib0 = s_in + bo0 * ISTRIDE;
        const float* ib1 = s_in + bo1 * ISTRIDE;

        float4 nA0 = *(const float4*)(ib0 + 128), nB0 = *(const float4*)(ib0 + 132);
        float4 nA1 = *(const float4*)(ib1 + 128), nB1 = *(const float4*)(ib1 + 132);
        float nk0[8] = {nA0.x, nA0.y, nA0.z, nA0.w, nB0.x, nB0.y, nB0.z, nB0.w};
        float nk1[8] = {nA1.x, nA1.y, nA1.z, nA1.w, nB1.x, nB1.y, nB1.z, nB1.w};

        float ibest0 = 3.402823466e38f, ibest1 = 3.402823466e38f;
        int   bk0 = 0, bk1 = 0;

        #pragma unroll
        for (int k = 0; k < NCPCC; k++) {
            const ulonglong2* kp0 = (const ulonglong2*)(ib0 + k * D2C);
            const ulonglong2* kp1 = (const ulonglong2*)(ib1 + k * D2C);
            ulonglong2 m00 = kp0[0], m01 = kp0[1], m02 = kp0[2], m03 = kp0[3];
            ulonglong2 m10 = kp1[0], m11 = kp1[1], m12 = kp1[2], m13 = kp1[3];

            u64 a0 = ffma2(py0[0], m00.x, 0ull);
            u64 a1 = ffma2(py1[0], m10.x, 0ull);
            a0 = ffma2(py0[1], m00.y, a0);  a1 = ffma2(py1[1], m10.y, a1);
            a0 = ffma2(py0[2], m01.x, a0);  a1 = ffma2(py1[2], m11.x, a1);
            a0 = ffma2(py0[3], m01.y, a0);  a1 = ffma2(py1[3], m11.y, a1);
            a0 = ffma2(py0[4], m02.x, a0);  a1 = ffma2(py1[4], m12.x, a1);
            a0 = ffma2(py0[5], m02.y, a0);  a1 = ffma2(py1[5], m12.y, a1);
            a0 = ffma2(py0[6], m03.x, a0);  a1 = ffma2(py1[6], m13.x, a1);
            a0 = ffma2(py0[7], m03.y, a0);  a1 = ffma2(py1[7], m13.y, a1);

            float dd0 = fmaf(-2.f, hsum2(a0), nk0[k]);
            float dd1 = fmaf(-2.f, hsum2(a1), nk1[k]);
            if (dd0 < ibest0) { ibest0 = dd0; bk0 = k; }
            if (dd1 < ibest1) { ibest1 = dd1; bk1 = k; }
        }

        out[i0] = (float)(bo0 * NCPCC + bk0);
        if (has1) out[i1] = (float)(bo1 * NCPCC + bk1);
    }
}

extern "C" void kernel_launch(void* const* d_in, const int* in_sizes, int n_in,
                              void* d_out, int out_size)
{
    // Bind inputs by unique element counts (robust to metadata ordering).
    const float* x  = 0; const float* co = 0; const float* ci = 0;
    long long x_elems = 0;
    for (int i = 0; i < n_in; i++) {
        int sz = in_sizes[i];
        if (sz == NCC * D1C)              co = (const float*)d_in[i];
        else if (sz == NCC * NCPCC * D2C) ci = (const float*)d_in[i];
        else { x = (const float*)d_in[i]; x_elems = sz; }
    }
    if (!x)  { x  = (const float*)d_in[0]; x_elems = in_sizes[0]; }
    if (!co)   co = (const float*)d_in[1];
    if (!ci)   ci = (const float*)d_in[2];

    float* out = (float*)d_out;
    int n = (int)(x_elems / (D1C + D2C));
    if (n <= 0 || n > out_size) n = out_size;

    int blocks = 296;  // 148 SMs x 2 CTAs (smem/regs cap), grid-stride, P=2 per thread
    cluster_kernel<<<blocks, 256>>>(x, co, ci, out, n);
}